// round 9
// baseline (speedup 1.0000x reference)
#include <cuda_runtime.h>
#include <cuda_bf16.h>
#include <cstdint>

#define D      128
#define DO2    256
#define NODES  50000
#define LN_EPS 1e-5f

#define CAP    64
#define SPILL_MAX 8192

#define MTILE  64
#define GRID_G ((NODES + MTILE - 1) / MTILE) // 782

#define XROW_W 68
#define XTILE_W (64 * XROW_W)
#define SMEM_GEMM (4 * XTILE_W * 4)     // 69632 bytes

#define NKS    8

// Scratch
__device__ int      g_cnt[NODES];
__device__ int2     g_slots[NODES * CAP];
__device__ int4     g_spill[SPILL_MAX];
__device__ int      g_nspill;
// W fragments, LDG.128-packed: uint4[half][nt(16)][ks(8)][lane(32)]
__device__ uint4    g_Wfrag[2 * 16 * NKS * 32];

// ---------------------------------------------------------------------------
__device__ __forceinline__ uint32_t pack_bf2(__nv_bfloat16 lo, __nv_bfloat16 hi) {
    return (uint32_t)__bfloat16_as_ushort(hi) << 16 | (uint32_t)__bfloat16_as_ushort(lo);
}

__device__ __forceinline__ void mma_bf16(float& d0, float& d1, float& d2, float& d3,
                                         uint32_t a0, uint32_t a1, uint32_t a2, uint32_t a3,
                                         uint32_t b0, uint32_t b1) {
    asm volatile(
        "mma.sync.aligned.m16n8k16.row.col.f32.bf16.bf16.f32 "
        "{%0,%1,%2,%3}, {%4,%5,%6,%7}, {%8,%9}, {%0,%1,%2,%3};"
        : "+f"(d0), "+f"(d1), "+f"(d2), "+f"(d3)
        : "r"(a0), "r"(a1), "r"(a2), "r"(a3), "r"(b0), "r"(b1));
}

// Convert float4 (features 4q..4q+3) to hi/lo bf16 packs and store to a tile row
__device__ __forceinline__ void store_bf16_split(uint32_t* tHi, uint32_t* tLo,
                                                 int q4, float4 x) {
    __nv_bfloat16 hx = __float2bfloat16_rn(x.x);
    __nv_bfloat16 hy = __float2bfloat16_rn(x.y);
    __nv_bfloat16 hz = __float2bfloat16_rn(x.z);
    __nv_bfloat16 hw = __float2bfloat16_rn(x.w);
    __nv_bfloat16 lx = __float2bfloat16_rn(x.x - __bfloat162float(hx));
    __nv_bfloat16 ly = __float2bfloat16_rn(x.y - __bfloat162float(hy));
    __nv_bfloat16 lz = __float2bfloat16_rn(x.z - __bfloat162float(hz));
    __nv_bfloat16 lw = __float2bfloat16_rn(x.w - __bfloat162float(hw));
    tHi[2 * q4]     = pack_bf2(hx, hy);
    tHi[2 * q4 + 1] = pack_bf2(hz, hw);
    tLo[2 * q4]     = pack_bf2(lx, ly);
    tLo[2 * q4 + 1] = pack_bf2(lz, lw);
}

// ---------------------------------------------------------------------------
// prep: zero counters + build packed bf16-split W fragments.
__global__ void prep_kernel(const float* __restrict__ Ws,
                            const float* __restrict__ Wn) {
    int idx = blockIdx.x * blockDim.x + threadIdx.x;
    if (idx < NODES) g_cnt[idx] = 0;
    if (idx == 0) g_nspill = 0;
    if (idx < 2 * 16 * NKS * 32 * 4) {
        int w    = idx & 3;
        int lane = (idx >> 2) & 31;
        int ks   = (idx >> 7) & 7;
        int nt   = (idx >> 10) & 15;
        int half = (idx >> 14) & 1;
        int p    = w >> 1;
        int reg  = w & 1;
        int n    = nt * 8 + (lane >> 2);
        int k    = ks * 16 + reg * 8 + 2 * (lane & 3);
        const float* W = half ? Wn : Ws;
        float w0 = W[n * D + k];
        float w1 = W[n * D + k + 1];
        __nv_bfloat16 h0 = __float2bfloat16_rn(w0);
        __nv_bfloat16 h1 = __float2bfloat16_rn(w1);
        __nv_bfloat16 v0, v1;
        if (p == 0) { v0 = h0; v1 = h1; }
        else {
            v0 = __float2bfloat16_rn(w0 - __bfloat162float(h0));
            v1 = __float2bfloat16_rn(w1 - __bfloat162float(h1));
        }
        reinterpret_cast<uint32_t*>(g_Wfrag)[idx] = pack_bf2(v0, v1);
    }
}

// ---------------------------------------------------------------------------
__global__ void scatter_kernel(const int*  __restrict__ row,
                               const int*  __restrict__ col,
                               const float* __restrict__ val,
                               int E) {
    int e = blockIdx.x * blockDim.x + threadIdx.x;
    if (e >= E) return;
    int r = row[e];
    int slot = atomicAdd(&g_cnt[r], 1);
    if (slot < CAP) {
        g_slots[r * CAP + slot] = make_int2(col[e], __float_as_int(val[e]));
    } else {
        int sp = atomicAdd(&g_nspill, 1);
        if (sp < SPILL_MAX)
            g_spill[sp] = make_int4(r, col[e], __float_as_int(val[e]), 0);
    }
}

// ---------------------------------------------------------------------------
// Fully fused: SpMM gather + bf16x3 tensor GEMM + concat + ReLU + LayerNorm.
// 256 threads, 64 nodes/CTA.
__global__ __launch_bounds__(256)
void fused_kernel(const float* __restrict__ h,
                  const float* __restrict__ b_self,
                  const float* __restrict__ b_neigh,
                  const float* __restrict__ gamma,
                  const float* __restrict__ beta,
                  float* __restrict__ out) {
    extern __shared__ uint32_t sX[];        // [half*2+part][64][68] words
    __shared__ float sSum[2][64];
    __shared__ float sSq[2][64];

    const int tid   = threadIdx.x;
    const int wid   = tid >> 5;
    const int lane  = tid & 31;
    const int node0 = blockIdx.x * MTILE;

    // Phase 1: stage h tile (half 0)
    for (int i = tid; i < 64 * 32; i += 256) {
        int row = i >> 5;
        int q4  = i & 31;
        int gn  = node0 + row;
        float4 x = (gn < NODES)
                 ? __ldg(reinterpret_cast<const float4*>(h + (size_t)gn * D) + q4)
                 : make_float4(0.f, 0.f, 0.f, 0.f);
        store_bf16_split(sX + 0 * XTILE_W + row * XROW_W,
                         sX + 1 * XTILE_W + row * XROW_W, q4, x);
    }

    // Phase 2: gather support rows (half 1). Warp w owns rows w*8..w*8+7,
    // processed in 2 groups of 4 simultaneous rows for MLP.
    #pragma unroll
    for (int g = 0; g < 2; g++) {
        int   row0 = wid * 8 + g * 4;
        float4 acc[4];
        int    cnt[4], base[4], over[4];
        #pragma unroll
        for (int r = 0; r < 4; r++) {
            acc[r] = make_float4(0.f, 0.f, 0.f, 0.f);
            int gn = node0 + row0 + r;
            int c  = (gn < NODES) ? g_cnt[gn] : 0;
            over[r] = (c > CAP);
            if (c > CAP) c = CAP;
            cnt[r]  = c;
            base[r] = (gn < NODES) ? gn * CAP : 0;
        }
        int maxc = max(max(cnt[0], cnt[1]), max(cnt[2], cnt[3]));

        int2 cv[4];
        #pragma unroll
        for (int r = 0; r < 4; r++)
            cv[r] = (cnt[r] > 0) ? __ldg(&g_slots[base[r]]) : make_int2(0, 0);

        for (int e = 0; e < maxc; e++) {
            int2 cur[4];
            #pragma unroll
            for (int r = 0; r < 4; r++) cur[r] = cv[r];
            #pragma unroll
            for (int r = 0; r < 4; r++)
                if (e + 1 < cnt[r]) cv[r] = __ldg(&g_slots[base[r] + e + 1]);
            float4 xv[4];
            #pragma unroll
            for (int r = 0; r < 4; r++)
                if (e < cnt[r])
                    xv[r] = __ldg(reinterpret_cast<const float4*>(
                                      h + (size_t)cur[r].x * D) + lane);
            #pragma unroll
            for (int r = 0; r < 4; r++) {
                if (e < cnt[r]) {
                    float v = __int_as_float(cur[r].y);
                    acc[r].x = fmaf(v, xv[r].x, acc[r].x);
                    acc[r].y = fmaf(v, xv[r].y, acc[r].y);
                    acc[r].z = fmaf(v, xv[r].z, acc[r].z);
                    acc[r].w = fmaf(v, xv[r].w, acc[r].w);
                }
            }
        }
        // Rare spill fold
        #pragma unroll
        for (int r = 0; r < 4; r++) {
            if (over[r]) {
                int gn = node0 + row0 + r;
                int n = g_nspill; if (n > SPILL_MAX) n = SPILL_MAX;
                for (int i = 0; i < n; i++) {
                    int4 s = g_spill[i];
                    if (s.x == gn) {
                        float v = __int_as_float(s.z);
                        float4 x = __ldg(reinterpret_cast<const float4*>(
                                             h + (size_t)s.y * D) + lane);
                        acc[r].x = fmaf(v, x.x, acc[r].x);
                        acc[r].y = fmaf(v, x.y, acc[r].y);
                        acc[r].z = fmaf(v, x.z, acc[r].z);
                        acc[r].w = fmaf(v, x.w, acc[r].w);
                    }
                }
            }
        }
        #pragma unroll
        for (int r = 0; r < 4; r++) {
            int row = row0 + r;
            store_bf16_split(sX + 2 * XTILE_W + row * XROW_W,
                             sX + 3 * XTILE_W + row * XROW_W, lane, acc[r]);
        }
    }
    __syncthreads();

    // Phase 3: mma + epilogue
    const int half = wid >> 2;
    const int mr   = (wid & 3) * 16;
    const int gr   = lane >> 2;
    const int q    = lane & 3;

    float acc[16][4];
    #pragma unroll
    for (int nt = 0; nt < 16; nt++)
        acc[nt][0] = acc[nt][1] = acc[nt][2] = acc[nt][3] = 0.f;

    const uint32_t* aHi = sX + (half * 2 + 0) * XTILE_W + (mr + gr) * XROW_W + q;
    const uint32_t* aLo = sX + (half * 2 + 1) * XTILE_W + (mr + gr) * XROW_W + q;
    const uint4* bBase = g_Wfrag + half * (16 * NKS * 32) + lane;

    #pragma unroll
    for (int ks = 0; ks < NKS; ks++) {
        const int ko = ks * 8;
        uint32_t a0h = aHi[ko],     a1h = aHi[ko + 8 * XROW_W];
        uint32_t a2h = aHi[ko + 4], a3h = aHi[ko + 4 + 8 * XROW_W];
        uint32_t a0l = aLo[ko],     a1l = aLo[ko + 8 * XROW_W];
        uint32_t a2l = aLo[ko + 4], a3l = aLo[ko + 4 + 8 * XROW_W];
        const uint4* bp = bBase + ks * 32;
        #pragma unroll
        for (int nt = 0; nt < 16; nt++) {
            uint4 b = __ldg(bp + nt * (NKS * 32));
            mma_bf16(acc[nt][0], acc[nt][1], acc[nt][2], acc[nt][3],
                     a0h, a1h, a2h, a3h, b.x, b.y);
            mma_bf16(acc[nt][0], acc[nt][1], acc[nt][2], acc[nt][3],
                     a0h, a1h, a2h, a3h, b.z, b.w);
            mma_bf16(acc[nt][0], acc[nt][1], acc[nt][2], acc[nt][3],
                     a0l, a1l, a2l, a3l, b.x, b.y);
        }
    }

    const float2* bb = reinterpret_cast<const float2*>(half ? b_neigh : b_self);
    float sA = 0.f, qA = 0.f, sB = 0.f, qB = 0.f;
    #pragma unroll
    for (int nt = 0; nt < 16; nt++) {
        float2 bv = __ldg(bb + nt * 4 + q);
        float v0 = fmaxf(acc[nt][0] + bv.x, 0.f);
        float v1 = fmaxf(acc[nt][1] + bv.y, 0.f);
        float v2 = fmaxf(acc[nt][2] + bv.x, 0.f);
        float v3 = fmaxf(acc[nt][3] + bv.y, 0.f);
        acc[nt][0] = v0; acc[nt][1] = v1; acc[nt][2] = v2; acc[nt][3] = v3;
        sA += v0 + v1;  qA += v0 * v0 + v1 * v1;
        sB += v2 + v3;  qB += v2 * v2 + v3 * v3;
    }
    #pragma unroll
    for (int o = 1; o <= 2; o <<= 1) {
        sA += __shfl_xor_sync(0xffffffffu, sA, o);
        qA += __shfl_xor_sync(0xffffffffu, qA, o);
        sB += __shfl_xor_sync(0xffffffffu, sB, o);
        qB += __shfl_xor_sync(0xffffffffu, qB, o);
    }
    if (q == 0) {
        sSum[half][mr + gr]     = sA;  sSq[half][mr + gr]     = qA;
        sSum[half][mr + gr + 8] = sB;  sSq[half][mr + gr + 8] = qB;
    }
    __syncthreads();

    int rowA = mr + gr, rowB = mr + gr + 8;
    float muA = (sSum[0][rowA] + sSum[1][rowA]) * (1.f / 256.f);
    float vaA = (sSq[0][rowA] + sSq[1][rowA]) * (1.f / 256.f) - muA * muA;
    float rsA = rsqrtf(vaA + LN_EPS);
    float muB = (sSum[0][rowB] + sSum[1][rowB]) * (1.f / 256.f);
    float vaB = (sSq[0][rowB] + sSq[1][rowB]) * (1.f / 256.f) - muB * muB;
    float rsB = rsqrtf(vaB + LN_EPS);

    const float2* gg = reinterpret_cast<const float2*>(gamma) + half * 64;
    const float2* ee = reinterpret_cast<const float2*>(beta)  + half * 64;
    int gnA = node0 + rowA;
    int gnB = node0 + rowB;
    #pragma unroll
    for (int nt = 0; nt < 16; nt++) {
        float2 gv = __ldg(gg + nt * 4 + q);
        float2 ev = __ldg(ee + nt * 4 + q);
        int coff = half * 128 + nt * 8 + 2 * q;
        if (gnA < NODES) {
            float2 o;
            o.x = (acc[nt][0] - muA) * rsA * gv.x + ev.x;
            o.y = (acc[nt][1] - muA) * rsA * gv.y + ev.y;
            *reinterpret_cast<float2*>(out + (size_t)gnA * DO2 + coff) = o;
        }
        if (gnB < NODES) {
            float2 o;
            o.x = (acc[nt][2] - muB) * rsB * gv.x + ev.x;
            o.y = (acc[nt][3] - muB) * rsB * gv.y + ev.y;
            *reinterpret_cast<float2*>(out + (size_t)gnB * DO2 + coff) = o;
        }
    }
}

// ---------------------------------------------------------------------------
extern "C" void kernel_launch(void* const* d_in, const int* in_sizes, int n_in,
                              void* d_out, int out_size) {
    const float* h        = (const float*)d_in[0];
    const int*   edge_row = (const int*)  d_in[1];
    const int*   edge_col = (const int*)  d_in[2];
    const float* edge_val = (const float*)d_in[3];
    const float* W_self   = (const float*)d_in[4];
    const float* b_self   = (const float*)d_in[5];
    const float* W_neigh  = (const float*)d_in[6];
    const float* b_neigh  = (const float*)d_in[7];
    const float* ln_gamma = (const float*)d_in[8];
    const float* ln_beta  = (const float*)d_in[9];
    float*       out      = (float*)d_out;

    const int E  = in_sizes[1];
    const int eb = (E + 255) / 256;

    static bool attr_done = false;
    if (!attr_done) {
        cudaFuncSetAttribute(fused_kernel,
                             cudaFuncAttributeMaxDynamicSharedMemorySize, SMEM_GEMM);
        attr_done = true;
    }

    prep_kernel<<<256, 256>>>(W_self, W_neigh);
    scatter_kernel<<<eb, 256>>>(edge_row, edge_col, edge_val, E);
    fused_kernel<<<GRID_G, 256, SMEM_GEMM>>>(h, b_self, b_neigh,
                                             ln_gamma, ln_beta, out);
}